// round 4
// baseline (speedup 1.0000x reference)
#include <cuda_runtime.h>
#include <cstdint>

// Problem constants
#define B_   4
#define N_   24
#define C_   256
#define H_   100
#define W_   100
#define OUT_ 7
#define P_   276                    // N*(N-1)/2
#define CH_  (C_ * OUT_ * OUT_)     // 12544 floats per [C,7,7] chunk
#define CH_BYTES_ (CH_ * 4)         // 50176 bytes
#define HW_  (H_ * W_)
#define SCALE_ 0.25f
#define TOT_ROIS_ (B_ * (N_ + P_)) // 1200
#define GRID_    304               // 2 CTAs per SM on 152-SM GB300
#define THREADS_ 512

// NHWC scratch for features
__device__ float g_nhwc[(size_t)B_ * HW_ * C_];

// ---------------------------------------------------------------------------
// PTX helpers
// ---------------------------------------------------------------------------
__device__ __forceinline__ uint32_t smem_u32(const void* p) {
    uint32_t a;
    asm("{ .reg .u64 t; cvta.to.shared.u64 t, %1; cvt.u32.u64 %0, t; }"
        : "=r"(a) : "l"(p));
    return a;
}
__device__ __forceinline__ void bulk_s2g(void* gmem, uint32_t smem, uint32_t bytes) {
    asm volatile("cp.async.bulk.global.shared::cta.bulk_group [%0], [%1], %2;"
                 :: "l"(gmem), "r"(smem), "r"(bytes) : "memory");
}
__device__ __forceinline__ void bulk_commit() {
    asm volatile("cp.async.bulk.commit_group;" ::: "memory");
}
__device__ __forceinline__ void bulk_wait_read1() {
    asm volatile("cp.async.bulk.wait_group.read 1;" ::: "memory");
}
__device__ __forceinline__ void bulk_wait_all0() {
    asm volatile("cp.async.bulk.wait_group 0;" ::: "memory");
}
__device__ __forceinline__ void fence_proxy_async_shared() {
    asm volatile("fence.proxy.async.shared::cta;" ::: "memory");
}

// ---------------------------------------------------------------------------
// Kernel 1: NCHW -> NHWC transpose, float4 stores.
// ---------------------------------------------------------------------------
__global__ void nchw_to_nhwc_kernel(const float* __restrict__ in) {
    __shared__ float tile[32][33];
    const int b   = blockIdx.z;
    const int c0  = blockIdx.y * 32;
    const int hw0 = blockIdx.x * 32;
    const int tx = threadIdx.x, ty = threadIdx.y;   // (32, 8)
    const int tid = ty * 32 + tx;

    const float* src = in + (size_t)b * C_ * HW_;
#pragma unroll
    for (int i = 0; i < 32; i += 8) {
        const int c  = c0 + ty + i;
        const int hw = hw0 + tx;
        float v = 0.0f;
        if (hw < HW_) v = src[(size_t)c * HW_ + hw];
        tile[ty + i][tx] = v;
    }
    __syncthreads();

    const int tx8 = tid & 7;     // float4 channel group
    const int tyy = tid >> 3;    // hw within tile
    const int hw  = hw0 + tyy;
    if (hw < HW_) {
        float4 v;
        v.x = tile[4 * tx8 + 0][tyy];
        v.y = tile[4 * tx8 + 1][tyy];
        v.z = tile[4 * tx8 + 2][tyy];
        v.w = tile[4 * tx8 + 3][tyy];
        float* dst = g_nhwc + (size_t)b * HW_ * C_;
        *reinterpret_cast<float4*>(&dst[(size_t)hw * C_ + c0 + 4 * tx8]) = v;
    }
}

// ---------------------------------------------------------------------------
// Kernel 2: persistent, double-buffered. Each CTA loops over rois strided by
// GRID_. Phase B computes pooled [C,7,7] into sbuf[it&1]; Phase C issues TMA
// bulk stores (fan-out) and the drain overlaps the NEXT roi's compute.
// Double-buffer protocol: every thread commits exactly one bulk_group per
// iteration (possibly empty), so wait_group.read 1 at iteration top drains
// all groups from >= 2 iterations ago, i.e. the buffer being overwritten.
// ---------------------------------------------------------------------------
__global__ __launch_bounds__(THREADS_, 2) void roi_pair_persistent(
    const float* __restrict__ boxes,   // [B, N, 4] xyxy, image coords
    float* __restrict__ out)           // [B*P, 3, C, 7, 7]
{
    extern __shared__ __align__(16) float sbuf[];  // 2 * CH_ floats
    __shared__ int   sy0[14], sy1[14], sx0[14], sx1[14];
    __shared__ float sly[14], shy[14], slx[14], shx[14];

    const int tid   = threadIdx.x;
    const int c4    = tid & 63;          // float4 channel group 0..63
    const int slotw = tid >> 6;          // 0..7
    const int oct   = (tid >> 3) & 3;    // lane octet
    const int res   = (slotw + oct) & 7; // bin residue mod 8 (skewed)

    int it = 0;
    for (int r = blockIdx.x; r < TOT_ROIS_; r += GRID_, ++it) {
        float* buf = sbuf + (it & 1) * CH_;

        // Drain groups from 2 iterations ago -> buf is free to overwrite.
        bulk_wait_read1();
        __syncthreads();   // also guards table overwrite vs prior-iter readers

        int b, m;  // batch, roi index (m < N_: object, else union pair m-N_)
        if (r < B_ * N_) { b = r / N_; m = r % N_; }
        else { const int u = r - B_ * N_; b = u / P_; m = N_ + (u % P_); }

        // Separable sample tables (28 threads, each decodes the box itself).
        if (tid < 28) {
            float x1, y1, x2, y2;
            if (m < N_) {
                const float* bx = boxes + ((size_t)b * N_ + m) * 4;
                x1 = bx[0]; y1 = bx[1]; x2 = bx[2]; y2 = bx[3];
            } else {
                int p = m - N_;
                int i = 0, rem = p, cnt = N_ - 1;
                while (rem >= cnt) { rem -= cnt; ++i; --cnt; }
                const int j = i + 1 + rem;
                const float* ba = boxes + ((size_t)b * N_ + i) * 4;
                const float* bb = boxes + ((size_t)b * N_ + j) * 4;
                x1 = fminf(ba[0], bb[0]);
                y1 = fminf(ba[1], bb[1]);
                x2 = fmaxf(ba[2], bb[2]);
                y2 = fmaxf(ba[3], bb[3]);
            }
            const int  d   = tid % 14;
            const bool isY = (tid >= 14);
            const float c1 = (isY ? y1 : x1) * SCALE_;
            const float c2 = (isY ? y2 : x2) * SCALE_;
            const float sz  = fmaxf(c2 - c1, 1.0f);
            const float bsz = sz * (1.0f / OUT_);
            const float g = (float)(d >> 1) + ((float)(d & 1) + 0.5f) * 0.5f;
            const float X = c1 + g * bsz;
            const int   lim = isY ? H_ : W_;
            const bool  valid = (X > -1.0f) && (X < (float)lim);
            const float Xc  = fminf(fmaxf(X, 0.0f), (float)(lim - 1));
            const float x0f = floorf(Xc);
            float lx = Xc - x0f;
            float hx = 1.0f - lx;
            if (!valid) { lx = 0.0f; hx = 0.0f; }
            const int t0  = (int)x0f;
            const int t1  = min(t0 + 1, lim - 1);
            if (isY) { sy0[d] = t0; sy1[d] = t1; sly[d] = lx; shy[d] = hx; }
            else     { sx0[d] = t0; sx1[d] = t1; slx[d] = lx; shx[d] = hx; }
        }
        __syncthreads();

        // Phase B: pooled compute. Each (slot,oct) covers residue res; per
        // octet the 8 lanes load a contiguous 128B channel segment.
        const float4* __restrict__ feat =
            reinterpret_cast<const float4*>(g_nhwc) + (size_t)b * HW_ * (C_ / 4);

#pragma unroll 1
        for (int t = 0; t < 7; ++t) {
            const int bin = 8 * t + res;
            if (bin >= OUT_ * OUT_) break;
            const int py = bin / OUT_;
            const int px = bin - py * OUT_;
            float4 acc = make_float4(0.f, 0.f, 0.f, 0.f);
#pragma unroll
            for (int sy = 0; sy < 2; ++sy) {
                const int   yi = 2 * py + sy;
                const int   y0 = sy0[yi], y1 = sy1[yi];
                const float ly = sly[yi], hy = shy[yi];
                const int r0 = y0 * W_;
                const int r1 = y1 * W_;
#pragma unroll
                for (int sx = 0; sx < 2; ++sx) {
                    const int   xi = 2 * px + sx;
                    const int   x0 = sx0[xi], x1 = sx1[xi];
                    const float lx = slx[xi], hx = shx[xi];
                    const float4 f00 = feat[(size_t)(r0 + x0) * 64 + c4];
                    const float4 f01 = feat[(size_t)(r0 + x1) * 64 + c4];
                    const float4 f10 = feat[(size_t)(r1 + x0) * 64 + c4];
                    const float4 f11 = feat[(size_t)(r1 + x1) * 64 + c4];
                    const float w00 = hy * hx, w01 = hy * lx, w10 = ly * hx, w11 = ly * lx;
                    acc.x += w00 * f00.x + w01 * f01.x + w10 * f10.x + w11 * f11.x;
                    acc.y += w00 * f00.y + w01 * f01.y + w10 * f10.y + w11 * f11.y;
                    acc.z += w00 * f00.z + w01 * f01.z + w10 * f10.z + w11 * f11.z;
                    acc.w += w00 * f00.w + w01 * f01.w + w10 * f10.w + w11 * f11.w;
                }
            }
            const int base = (4 * c4) * 49 + bin;   // bank-conflict-free STS
            buf[base]       = acc.x * 0.25f;
            buf[base + 49]  = acc.y * 0.25f;
            buf[base + 98]  = acc.z * 0.25f;
            buf[base + 147] = acc.w * 0.25f;
        }
        __syncthreads();

        // Phase C: issue TMA bulk stores; do NOT wait here (overlap).
        const uint32_t psrc = smem_u32(buf);
        if (m < N_) {
            if (tid < N_ - 1) {
                fence_proxy_async_shared();
                int p, slot_o;
                const int hi = N_ - 1 - m;
                if (tid < hi) {
                    const int j = m + 1 + tid;
                    p = m * (N_ - 1) - (m * (m - 1)) / 2 + (j - m - 1);
                    slot_o = 0;
                } else {
                    const int i = tid - hi;
                    p = i * (N_ - 1) - (i * (i - 1)) / 2 + (m - i - 1);
                    slot_o = 1;
                }
                float* dst = out + (((size_t)b * P_ + p) * 3 + slot_o) * CH_;
                bulk_s2g(dst, psrc, CH_BYTES_);
            }
        } else {
            if (tid == 0) {
                fence_proxy_async_shared();
                const int p = m - N_;
                float* dst = out + (((size_t)b * P_ + p) * 3 + 2) * CH_;
                bulk_s2g(dst, psrc, CH_BYTES_);
            }
        }
        bulk_commit();   // ALL threads: uniform per-thread group counts
    }

    bulk_wait_all0();    // full completion (writes visible) before exit
}

// ---------------------------------------------------------------------------
extern "C" void kernel_launch(void* const* d_in, const int* in_sizes, int n_in,
                              void* d_out, int out_size) {
    const float* features = (const float*)d_in[0];  // [B,C,H,W] float32
    const float* boxes    = (const float*)d_in[1];  // [B,N,4]   float32
    float* out = (float*)d_out;

    dim3 tgrid((HW_ + 31) / 32, C_ / 32, B_);
    nchw_to_nhwc_kernel<<<tgrid, dim3(32, 8)>>>(features);

    static bool attr_done = false;
    if (!attr_done) {
        cudaFuncSetAttribute(roi_pair_persistent,
                             cudaFuncAttributeMaxDynamicSharedMemorySize,
                             2 * CH_BYTES_);
        attr_done = true;
    }
    roi_pair_persistent<<<GRID_, THREADS_, 2 * CH_BYTES_>>>(boxes, out);
}

// round 7
// speedup vs baseline: 1.1737x; 1.1737x over previous
#include <cuda_runtime.h>
#include <cstdint>

// Problem constants
#define B_   4
#define N_   24
#define C_   256
#define H_   100
#define W_   100
#define OUT_ 7
#define P_   276                      // N*(N-1)/2
#define CH_  (C_ * OUT_ * OUT_)       // 12544 floats per full [C,7,7] chunk
#define HCH_ (CH_ / 2)                // 6272 floats per half-channel chunk
#define HW_  (H_ * W_)
#define SCALE_ 0.25f
#define NROIS_ (N_ + P_)              // 300 rois per batch

// NHWC scratch for features
__device__ float g_nhwc[(size_t)B_ * HW_ * C_];

// ---------------------------------------------------------------------------
// Kernel 1: NCHW -> NHWC transpose, float4 stores.
// ---------------------------------------------------------------------------
__global__ void nchw_to_nhwc_kernel(const float* __restrict__ in) {
    __shared__ float tile[32][33];
    const int b   = blockIdx.z;
    const int c0  = blockIdx.y * 32;
    const int hw0 = blockIdx.x * 32;
    const int tx = threadIdx.x, ty = threadIdx.y;   // (32, 8)
    const int tid = ty * 32 + tx;

    const float* src = in + (size_t)b * C_ * HW_;
#pragma unroll
    for (int i = 0; i < 32; i += 8) {
        const int c  = c0 + ty + i;
        const int hw = hw0 + tx;
        float v = 0.0f;
        if (hw < HW_) v = src[(size_t)c * HW_ + hw];
        tile[ty + i][tx] = v;
    }
    __syncthreads();

    const int tx8 = tid & 7;     // float4 channel group
    const int tyy = tid >> 3;    // hw within tile
    const int hw  = hw0 + tyy;
    if (hw < HW_) {
        float4 v;
        v.x = tile[4 * tx8 + 0][tyy];
        v.y = tile[4 * tx8 + 1][tyy];
        v.z = tile[4 * tx8 + 2][tyy];
        v.w = tile[4 * tx8 + 3][tyy];
        float* dst = g_nhwc + (size_t)b * HW_ * C_;
        *reinterpret_cast<float4*>(&dst[(size_t)hw * C_ + c0 + 4 * tx8]) = v;
    }
}

// ---------------------------------------------------------------------------
// Kernel 2: TWO CTAs per roi (one per 128-channel half). 256 threads.
// smem ~24.6KB, launch_bounds(256,6) -> 6 CTAs/SM = 48 warps (75% occ).
//  Phase A: roi decode + separable sample tables.
//  Phase B: pooled half-tile [128,7,7] in smem. c4 = tid&31 spans 32 float4
//           channel groups (one warp = one slot = contiguous 512B per tap).
//           Octet bin-skew keeps stride-196 STS conflict-free.
//  Phase C: plain float4 STG fan-out of the 24.5KB half-tile.
// ---------------------------------------------------------------------------
__global__ __launch_bounds__(256, 6) void roi_pair_kernel(
    const float* __restrict__ boxes,   // [B, N, 4] xyxy, image coords
    float* __restrict__ out)           // [B*P, 3, C, 7, 7]
{
    __shared__ __align__(16) float pooled[HCH_];
    __shared__ int   sy0[14], sy1[14], sx0[14], sx1[14];
    __shared__ float sly[14], shy[14], slx[14], shx[14];

    const int bid  = blockIdx.x;
    const int tid  = threadIdx.x;
    const int r    = bid >> 1;       // roi id 0..1199 (objects first)
    const int half = bid & 1;        // channel half

    int b, m;  // batch, roi index within batch (m < N_: object, else union)
    if (r < B_ * N_) { b = r / N_; m = r % N_; }
    else { const int u = r - B_ * N_; b = u / P_; m = N_ + (u % P_); }

    // Separable sample tables: tid 0..13 -> x, 14..27 -> y. Each of the 28
    // threads decodes the box itself (cheap, avoids an extra barrier).
    if (tid < 28) {
        float x1, y1, x2, y2;
        if (m < N_) {
            const float* bx = boxes + ((size_t)b * N_ + m) * 4;
            x1 = bx[0]; y1 = bx[1]; x2 = bx[2]; y2 = bx[3];
        } else {
            int p = m - N_;
            int i = 0, rem = p, cnt = N_ - 1;
            while (rem >= cnt) { rem -= cnt; ++i; --cnt; }
            const int j = i + 1 + rem;
            const float* ba = boxes + ((size_t)b * N_ + i) * 4;
            const float* bb = boxes + ((size_t)b * N_ + j) * 4;
            x1 = fminf(ba[0], bb[0]);
            y1 = fminf(ba[1], bb[1]);
            x2 = fmaxf(ba[2], bb[2]);
            y2 = fmaxf(ba[3], bb[3]);
        }
        const int  d   = tid % 14;
        const bool isY = (tid >= 14);
        const float c1 = (isY ? y1 : x1) * SCALE_;
        const float c2 = (isY ? y2 : x2) * SCALE_;
        const float sz  = fmaxf(c2 - c1, 1.0f);
        const float bsz = sz * (1.0f / OUT_);
        const float g = (float)(d >> 1) + ((float)(d & 1) + 0.5f) * 0.5f;
        const float X = c1 + g * bsz;
        const int   lim = isY ? H_ : W_;
        const bool  valid = (X > -1.0f) && (X < (float)lim);
        const float Xc  = fminf(fmaxf(X, 0.0f), (float)(lim - 1));
        const float x0f = floorf(Xc);
        float lx = Xc - x0f;
        float hx = 1.0f - lx;
        if (!valid) { lx = 0.0f; hx = 0.0f; }
        const int t0 = (int)x0f;
        const int t1 = min(t0 + 1, lim - 1);
        if (isY) { sy0[d] = t0; sy1[d] = t1; sly[d] = lx; shy[d] = hx; }
        else     { sx0[d] = t0; sx1[d] = t1; slx[d] = lx; shx[d] = hx; }
    }
    __syncthreads();

    // Phase B.
    const int c4   = tid & 31;          // local float4 channel group 0..31
    const int slot = tid >> 5;          // warp id 0..7
    const int oct  = (tid >> 3) & 3;    // lane octet within warp
    const int res  = (slot + oct) & 7;  // bin residue mod 8; for fixed c4 the
                                        // 8 slots give 8 distinct residues.
    const float4* __restrict__ feat =
        reinterpret_cast<const float4*>(g_nhwc) +
        (size_t)b * HW_ * (C_ / 4) + half * 32 + c4;

#pragma unroll 1
    for (int t = 0; t < 7; ++t) {
        const int bin = 8 * t + res;
        if (bin >= OUT_ * OUT_) break;
        const int py = bin / OUT_;
        const int px = bin - py * OUT_;
        float4 acc = make_float4(0.f, 0.f, 0.f, 0.f);
#pragma unroll
        for (int sy = 0; sy < 2; ++sy) {
            const int   yi = 2 * py + sy;
            const int   y0 = sy0[yi], y1 = sy1[yi];
            const float ly = sly[yi], hy = shy[yi];
            const int r0 = y0 * W_;
            const int r1 = y1 * W_;
#pragma unroll
            for (int sx = 0; sx < 2; ++sx) {
                const int   xi = 2 * px + sx;
                const int   x0 = sx0[xi], x1 = sx1[xi];
                const float lx = slx[xi], hx = shx[xi];
                const float4 f00 = feat[(size_t)(r0 + x0) * 64];
                const float4 f01 = feat[(size_t)(r0 + x1) * 64];
                const float4 f10 = feat[(size_t)(r1 + x0) * 64];
                const float4 f11 = feat[(size_t)(r1 + x1) * 64];
                const float w00 = hy * hx, w01 = hy * lx, w10 = ly * hx, w11 = ly * lx;
                acc.x += w00 * f00.x + w01 * f01.x + w10 * f10.x + w11 * f11.x;
                acc.y += w00 * f00.y + w01 * f01.y + w10 * f10.y + w11 * f11.y;
                acc.z += w00 * f00.z + w01 * f01.z + w10 * f10.z + w11 * f11.z;
                acc.w += w00 * f00.w + w01 * f01.w + w10 * f10.w + w11 * f11.w;
            }
        }
        // bank = (4*(8*oct+k) + bin) mod 32 = 4k + (res mod 4): conflict-free.
        const int base = (4 * c4) * 49 + bin;
        pooled[base]       = acc.x * 0.25f;
        pooled[base + 49]  = acc.y * 0.25f;
        pooled[base + 98]  = acc.z * 0.25f;
        pooled[base + 147] = acc.w * 0.25f;
    }
    __syncthreads();

    // Phase C: float4 STG fan-out of the half-tile.
    const float4* __restrict__ psrc = reinterpret_cast<const float4*>(pooled);
    const int NV = HCH_ / 4;  // 1568
    float4* outv = reinterpret_cast<float4*>(out);
    const int hoff = half * NV;   // float4 offset of this channel half
    if (m < N_) {
        for (int j = m + 1; j < N_; ++j) {
            const int p = m * (N_ - 1) - (m * (m - 1)) / 2 + (j - m - 1);
            float4* dst = outv + (((size_t)b * P_ + p) * 3 + 0) * (CH_ / 4) + hoff;
            for (int idx = tid; idx < NV; idx += 256) dst[idx] = psrc[idx];
        }
        for (int i = 0; i < m; ++i) {
            const int p = i * (N_ - 1) - (i * (i - 1)) / 2 + (m - i - 1);
            float4* dst = outv + (((size_t)b * P_ + p) * 3 + 1) * (CH_ / 4) + hoff;
            for (int idx = tid; idx < NV; idx += 256) dst[idx] = psrc[idx];
        }
    } else {
        const int p = m - N_;
        float4* dst = outv + (((size_t)b * P_ + p) * 3 + 2) * (CH_ / 4) + hoff;
        for (int idx = tid; idx < NV; idx += 256) dst[idx] = psrc[idx];
    }
}

// ---------------------------------------------------------------------------
extern "C" void kernel_launch(void* const* d_in, const int* in_sizes, int n_in,
                              void* d_out, int out_size) {
    const float* features = (const float*)d_in[0];  // [B,C,H,W] float32
    const float* boxes    = (const float*)d_in[1];  // [B,N,4]   float32
    float* out = (float*)d_out;

    dim3 tgrid((HW_ + 31) / 32, C_ / 32, B_);
    nchw_to_nhwc_kernel<<<tgrid, dim3(32, 8)>>>(features);

    const int nblocks = 2 * B_ * NROIS_;   // 2400: 192 object CTAs first
    roi_pair_kernel<<<nblocks, 256>>>(boxes, out);
}

// round 8
// speedup vs baseline: 1.2045x; 1.0262x over previous
#include <cuda_runtime.h>
#include <cstdint>

// Problem constants
#define B_   4
#define N_   24
#define C_   256
#define H_   100
#define W_   100
#define OUT_ 7
#define P_   276                      // N*(N-1)/2
#define CH_  (C_ * OUT_ * OUT_)       // 12544 floats per full [C,7,7] chunk
#define HCH_ (CH_ / 2)                // 6272 floats per half-channel chunk
#define HW_  (H_ * W_)
#define SCALE_ 0.25f
#define NROIS_ (N_ + P_)              // 300 rois per batch
#define NV_   (HCH_ / 4)              // 1568 float4 per half tile
#define RPT_  7                       // ceil(1568/256) register slots per thread

// NHWC scratch for features
__device__ float g_nhwc[(size_t)B_ * HW_ * C_];

__device__ __forceinline__ void stcs4(float4* p, float4 v) {
    asm volatile("st.global.cs.v4.f32 [%0], {%1,%2,%3,%4};"
                 :: "l"(p), "f"(v.x), "f"(v.y), "f"(v.z), "f"(v.w) : "memory");
}

// ---------------------------------------------------------------------------
// Kernel 1: NCHW -> NHWC transpose, float4 stores.
// ---------------------------------------------------------------------------
__global__ void nchw_to_nhwc_kernel(const float* __restrict__ in) {
    __shared__ float tile[32][33];
    const int b   = blockIdx.z;
    const int c0  = blockIdx.y * 32;
    const int hw0 = blockIdx.x * 32;
    const int tx = threadIdx.x, ty = threadIdx.y;   // (32, 8)
    const int tid = ty * 32 + tx;

    const float* src = in + (size_t)b * C_ * HW_;
#pragma unroll
    for (int i = 0; i < 32; i += 8) {
        const int c  = c0 + ty + i;
        const int hw = hw0 + tx;
        float v = 0.0f;
        if (hw < HW_) v = src[(size_t)c * HW_ + hw];
        tile[ty + i][tx] = v;
    }
    __syncthreads();

    const int tx8 = tid & 7;     // float4 channel group
    const int tyy = tid >> 3;    // hw within tile
    const int hw  = hw0 + tyy;
    if (hw < HW_) {
        float4 v;
        v.x = tile[4 * tx8 + 0][tyy];
        v.y = tile[4 * tx8 + 1][tyy];
        v.z = tile[4 * tx8 + 2][tyy];
        v.w = tile[4 * tx8 + 3][tyy];
        float* dst = g_nhwc + (size_t)b * HW_ * C_;
        *reinterpret_cast<float4*>(&dst[(size_t)hw * C_ + c0 + 4 * tx8]) = v;
    }
}

// ---------------------------------------------------------------------------
// Kernel 2: TWO CTAs per roi (one per 128-channel half). 256 threads.
//  Phase B: pooled half-tile [128,7,7] into smem (octet bin-skew: STS
//           conflict-free, loads contiguous 128B per octet).
//  Phase C: stage half-tile into registers (one LDS pass), then streaming
//           STG.128 fan-out to every destination. No repeated smem reads.
// ---------------------------------------------------------------------------
__global__ __launch_bounds__(256, 5) void roi_pair_kernel(
    const float* __restrict__ boxes,   // [B, N, 4] xyxy, image coords
    float* __restrict__ out)           // [B*P, 3, C, 7, 7]
{
    __shared__ __align__(16) float pooled[HCH_];
    __shared__ int   sy0[14], sy1[14], sx0[14], sx1[14];
    __shared__ float sly[14], shy[14], slx[14], shx[14];

    const int bid  = blockIdx.x;
    const int tid  = threadIdx.x;
    const int r    = bid >> 1;       // roi id 0..1199 (objects first)
    const int half = bid & 1;        // channel half

    int b, m;  // batch, roi index within batch (m < N_: object, else union)
    if (r < B_ * N_) { b = r / N_; m = r % N_; }
    else { const int u = r - B_ * N_; b = u / P_; m = N_ + (u % P_); }

    // Separable sample tables: tid 0..13 -> x, 14..27 -> y.
    if (tid < 28) {
        float x1, y1, x2, y2;
        if (m < N_) {
            const float* bx = boxes + ((size_t)b * N_ + m) * 4;
            x1 = bx[0]; y1 = bx[1]; x2 = bx[2]; y2 = bx[3];
        } else {
            int p = m - N_;
            int i = 0, rem = p, cnt = N_ - 1;
            while (rem >= cnt) { rem -= cnt; ++i; --cnt; }
            const int j = i + 1 + rem;
            const float* ba = boxes + ((size_t)b * N_ + i) * 4;
            const float* bb = boxes + ((size_t)b * N_ + j) * 4;
            x1 = fminf(ba[0], bb[0]);
            y1 = fminf(ba[1], bb[1]);
            x2 = fmaxf(ba[2], bb[2]);
            y2 = fmaxf(ba[3], bb[3]);
        }
        const int  d   = tid % 14;
        const bool isY = (tid >= 14);
        const float c1 = (isY ? y1 : x1) * SCALE_;
        const float c2 = (isY ? y2 : x2) * SCALE_;
        const float sz  = fmaxf(c2 - c1, 1.0f);
        const float bsz = sz * (1.0f / OUT_);
        const float g = (float)(d >> 1) + ((float)(d & 1) + 0.5f) * 0.5f;
        const float X = c1 + g * bsz;
        const int   lim = isY ? H_ : W_;
        const bool  valid = (X > -1.0f) && (X < (float)lim);
        const float Xc  = fminf(fmaxf(X, 0.0f), (float)(lim - 1));
        const float x0f = floorf(Xc);
        float lx = Xc - x0f;
        float hx = 1.0f - lx;
        if (!valid) { lx = 0.0f; hx = 0.0f; }
        const int t0 = (int)x0f;
        const int t1 = min(t0 + 1, lim - 1);
        if (isY) { sy0[d] = t0; sy1[d] = t1; sly[d] = lx; shy[d] = hx; }
        else     { sx0[d] = t0; sx1[d] = t1; slx[d] = lx; shx[d] = hx; }
    }
    __syncthreads();

    // Phase B.
    const int c4   = tid & 31;          // local float4 channel group 0..31
    const int slot = tid >> 5;          // warp id 0..7
    const int oct  = (tid >> 3) & 3;    // lane octet within warp
    const int res  = (slot + oct) & 7;  // bin residue mod 8 (skewed)
    const float4* __restrict__ feat =
        reinterpret_cast<const float4*>(g_nhwc) +
        (size_t)b * HW_ * (C_ / 4) + half * 32 + c4;

#pragma unroll 1
    for (int t = 0; t < 7; ++t) {
        const int bin = 8 * t + res;
        if (bin >= OUT_ * OUT_) break;
        const int py = bin / OUT_;
        const int px = bin - py * OUT_;
        float4 acc = make_float4(0.f, 0.f, 0.f, 0.f);
#pragma unroll
        for (int sy = 0; sy < 2; ++sy) {
            const int   yi = 2 * py + sy;
            const int   y0 = sy0[yi], y1 = sy1[yi];
            const float ly = sly[yi], hy = shy[yi];
            const int r0 = y0 * W_;
            const int r1 = y1 * W_;
#pragma unroll
            for (int sx = 0; sx < 2; ++sx) {
                const int   xi = 2 * px + sx;
                const int   x0 = sx0[xi], x1 = sx1[xi];
                const float lx = slx[xi], hx = shx[xi];
                const float4 f00 = feat[(size_t)(r0 + x0) * 64];
                const float4 f01 = feat[(size_t)(r0 + x1) * 64];
                const float4 f10 = feat[(size_t)(r1 + x0) * 64];
                const float4 f11 = feat[(size_t)(r1 + x1) * 64];
                const float w00 = hy * hx, w01 = hy * lx, w10 = ly * hx, w11 = ly * lx;
                acc.x += w00 * f00.x + w01 * f01.x + w10 * f10.x + w11 * f11.x;
                acc.y += w00 * f00.y + w01 * f01.y + w10 * f10.y + w11 * f11.y;
                acc.z += w00 * f00.z + w01 * f01.z + w10 * f10.z + w11 * f11.z;
                acc.w += w00 * f00.w + w01 * f01.w + w10 * f10.w + w11 * f11.w;
            }
        }
        const int base = (4 * c4) * 49 + bin;   // conflict-free STS
        pooled[base]       = acc.x * 0.25f;
        pooled[base + 49]  = acc.y * 0.25f;
        pooled[base + 98]  = acc.z * 0.25f;
        pooled[base + 147] = acc.w * 0.25f;
    }
    __syncthreads();

    // Phase C: stage half-tile into registers ONCE, then STG-only fan-out.
    const float4* __restrict__ psrc = reinterpret_cast<const float4*>(pooled);
    float4 stage[RPT_];
#pragma unroll
    for (int k = 0; k < RPT_; ++k) {
        const int idx = tid + k * 256;
        if (idx < NV_) stage[k] = psrc[idx];
    }

    float4* outv = reinterpret_cast<float4*>(out);
    const int hoff = half * NV_;

    if (m < N_) {
#pragma unroll 1
        for (int q = 0; q < N_ - 1; ++q) {
            // q enumerates: first (N-1-m) partners j>m (slot 0), then i<m (slot 1)
            int p, slot_o;
            const int hi = N_ - 1 - m;
            if (q < hi) {
                const int j = m + 1 + q;
                p = m * (N_ - 1) - (m * (m - 1)) / 2 + (j - m - 1);
                slot_o = 0;
            } else {
                const int i = q - hi;
                p = i * (N_ - 1) - (i * (i - 1)) / 2 + (m - i - 1);
                slot_o = 1;
            }
            float4* dst = outv + (((size_t)b * P_ + p) * 3 + slot_o) * (CH_ / 4) + hoff;
#pragma unroll
            for (int k = 0; k < RPT_; ++k) {
                const int idx = tid + k * 256;
                if (idx < NV_) stcs4(&dst[idx], stage[k]);
            }
        }
    } else {
        const int p = m - N_;
        float4* dst = outv + (((size_t)b * P_ + p) * 3 + 2) * (CH_ / 4) + hoff;
#pragma unroll
        for (int k = 0; k < RPT_; ++k) {
            const int idx = tid + k * 256;
            if (idx < NV_) stcs4(&dst[idx], stage[k]);
        }
    }
}

// ---------------------------------------------------------------------------
extern "C" void kernel_launch(void* const* d_in, const int* in_sizes, int n_in,
                              void* d_out, int out_size) {
    const float* features = (const float*)d_in[0];  // [B,C,H,W] float32
    const float* boxes    = (const float*)d_in[1];  // [B,N,4]   float32
    float* out = (float*)d_out;

    dim3 tgrid((HW_ + 31) / 32, C_ / 32, B_);
    nchw_to_nhwc_kernel<<<tgrid, dim3(32, 8)>>>(features);

    const int nblocks = 2 * B_ * NROIS_;   // 2400: 192 object CTAs first
    roi_pair_kernel<<<nblocks, 256>>>(boxes, out);
}